// round 15
// baseline (speedup 1.0000x reference)
#include <cuda_runtime.h>
#include <cstdint>

#define SEQ    512
#define BATCH  1024
#define NTAG   64

__device__ __forceinline__ float ex2f_(float x) {
    float y; asm("ex2.approx.ftz.f32 %0, %1;" : "=f"(y) : "f"(x)); return y;
}
__device__ __forceinline__ float lg2f_(float x) {
    float y; asm("lg2.approx.ftz.f32 %0, %1;" : "=f"(y) : "f"(x)); return y;
}
__device__ __forceinline__ unsigned long long fma2_(unsigned long long a,
                                                    unsigned long long b,
                                                    unsigned long long c) {
    unsigned long long d;
    asm("fma.rn.f32x2 %0, %1, %2, %3;" : "=l"(d) : "l"(a), "l"(b), "l"(c));
    return d;
}
__device__ __forceinline__ unsigned long long add2_(unsigned long long a,
                                                    unsigned long long b) {
    unsigned long long d;
    asm("add.rn.f32x2 %0, %1, %2;" : "=l"(d) : "l"(a), "l"(b));
    return d;
}
__device__ __forceinline__ void unpack_(unsigned long long v, float& x, float& y) {
    asm("mov.b64 {%0, %1}, %2;" : "=f"(x), "=f"(y) : "l"(v));
}
__device__ __forceinline__ unsigned long long packf_(float x, float y) {
    unsigned long long r;
    asm("mov.b64 %0, {%1, %2};" : "=l"(r) : "f"(x), "f"(y));
    return r;
}
// bf16x2 word: lo f32 -> low half, hi f32 -> high half
__device__ __forceinline__ uint32_t bfpack_(float hi, float lo) {
    uint32_t r;
    asm("cvt.rn.satfinite.bf16x2.f32 %0, %1, %2;" : "=r"(r) : "f"(hi), "f"(lo));
    return r;
}
// expand bf16x2 word into f32x2 operand (low bf16 -> low lane, high -> high)
__device__ __forceinline__ unsigned long long bfexpand_(uint32_t q) {
    const uint32_t lo = q << 16;
    const uint32_t hi = q & 0xffff0000u;
    unsigned long long v;
    asm("mov.b64 %0, {%1, %2};" : "=l"(v) : "r"(lo), "r"(hi));
    return v;
}
__device__ __forceinline__ float wmax_(float v) {
#pragma unroll
    for (int d = 16; d; d >>= 1)
        v = fmaxf(v, __shfl_xor_sync(0xffffffffu, v, d));
    return v;
}
__device__ __forceinline__ int clampi_(int v, int lo, int hi) {
    return v < lo ? lo : (v > hi ? hi : v);
}

// One warp = one CTA = one batch, advancing BOTH sequence ends per iteration
// (R14 structure) with bf16x2 SHUFFLE TRANSPORT in both directions (R12 trick):
//   fwd gather:  v = expand(shfl(pk, r));  S_j += E2[j][i] * v
//   bwd scatter: c = E2[lane][i]*w_lo + E2[lane+32][i]*w_hi (f32x2);
//                ck = bf16x2(c); z += expand(shfl(ck, r))
// 64 SHFL per pair-iteration (was 128). One shared pre-permuted table.
// out = (C2f + C2b + lg2 <p_h, z_h>) * ln2 — exact split identity.
__global__ void __launch_bounds__(32)
crf_main(const float* __restrict__ feats,
         const float* __restrict__ mask,
         const float* __restrict__ trans,
         float* __restrict__ out) {
    const int lane = threadIdx.x;
    const int b    = blockIdx.x;

    const float LN2 = 0.6931471805599453f;
    const float L2E = 1.4426950408889634f;
    const float SH2 = 6.0f * L2E;             // constant per-step down-scale

    // ---- len = sum of this batch's monotone mask column ----
    float lsum = 0.0f;
#pragma unroll
    for (int t = 0; t < 16; ++t)
        lsum += __ldcs(mask + (size_t)(t * 32 + lane) * BATCH + b);
#pragma unroll
    for (int d = 16; d; d >>= 1)
        lsum += __shfl_xor_sync(0xffffffffu, lsum, d);
    const int len  = (int)(lsum + 0.5f);
    const int h    = (len + 1) >> 1;
    const int nstF = h;
    const int nstB = len - h;
    const int lenr = (h + 3) & ~3;

    // ---- ONE pre-permuted, pre-packed table (f32x2), i = lane^r ----
    unsigned long long EAC[32], EBD[32];
#pragma unroll
    for (int r = 0; r < 32; ++r) {
        const int i = lane ^ r;
        EAC[r] = packf_(__expf(__ldg(trans + lane * NTAG + i)),
                        __expf(__ldg(trans + lane * NTAG + 32 + i)));
        EBD[r] = packf_(__expf(__ldg(trans + (lane + 32) * NTAG + i)),
                        __expf(__ldg(trans + (lane + 32) * NTAG + 32 + i)));
    }

    // ---- feats pipelines (fwd ascending, bwd descending) ----
    const float* fs = feats + (size_t)b * NTAG + lane;   // step s at +s*65536
    float efFL[4], efFH[4], fFL[4], fFH[4];
    float efBL[4], efBH[4], fBL[4], fBH[4];
#pragma unroll
    for (int u = 0; u < 4; ++u) {
        const float* pf0 = fs + ((size_t)u << 16);
        efFL[u] = ex2f_(fmaf(__ldcs(pf0),      L2E, -SH2));
        efFH[u] = ex2f_(fmaf(__ldcs(pf0 + 32), L2E, -SH2));
        const float* pf1 = fs + ((size_t)(u + 4) << 16);
        fFL[u] = __ldcs(pf1);
        fFH[u] = __ldcs(pf1 + 32);
        const float* pb0 = fs + ((size_t)(len - 2 - u) << 16);
        efBL[u] = ex2f_(fmaf(__ldcs(pb0),      L2E, -SH2));
        efBH[u] = ex2f_(fmaf(__ldcs(pb0 + 32), L2E, -SH2));
        const float* pb1 = fs + ((size_t)(len - 6 - u) << 16);
        fBL[u] = __ldcs(pb1);
        fBH[u] = __ldcs(pb1 + 32);
    }
    int fidxF = 8;
    int fidxB = len - 10;

    // ---- states ----
    float pF_lo = (lane == 0) ? 1.0f : 0.0f;  // fwd vector (f32 master copy)
    float pF_hi = 0.0f;
    uint32_t pkF = bfpack_(pF_hi, pF_lo);     // fwd transport word
    float stF_lo = pF_lo, stF_hi = 0.0f;      // p_h candidate
    const float z_lo = __expf(trans[NTAG + lane]);        // z_len = exp(T[END][i])
    const float z_hi = __expf(trans[NTAG + 32 + lane]);
    float wB_lo, wB_hi;                        // bwd transported vector (f32)
    {
        const float* pl = fs + ((size_t)(len - 1) << 16);
        wB_lo = z_lo * ex2f_(fmaf(__ldcs(pl),      L2E, -SH2));
        wB_hi = z_hi * ex2f_(fmaf(__ldcs(pl + 32), L2E, -SH2));
    }
    float stB_lo = z_lo, stB_hi = z_hi;        // z_h candidate

    float C2f = 0.0f, rfF = 1.0f, lgF = 0.0f;
    float C2b = 0.0f, rfB = 1.0f, lgB = 0.0f;

#pragma unroll 1
    for (int s = 0; s < lenr; s += 4) {
#pragma unroll
        for (int u = 0; u < 4; ++u) {
            const unsigned long long wlo2 = packf_(wB_lo, wB_lo);
            const unsigned long long whi2 = packf_(wB_hi, wB_hi);
            unsigned long long aA0 = 0ull, aA1 = 0ull;   // fwd S partials
            unsigned long long aB0 = 0ull, aB1 = 0ull;
            unsigned long long zc0 = 0ull, zc1 = 0ull;   // bwd z partials
#pragma unroll
            for (int r = 0; r < 32; r += 2) {
                // fwd gather, round r : 1 SHFL
                {
                    const unsigned long long v =
                        bfexpand_(__shfl_xor_sync(0xffffffffu, pkF, r));
                    aA0 = fma2_(EAC[r], v, aA0);
                    aB0 = fma2_(EBD[r], v, aB0);
                }
                // bwd scatter, round r : 1 SHFL
                {
                    const unsigned long long c =
                        fma2_(EAC[r], wlo2, fma2_(EBD[r], whi2, 0ull));
                    float cx, cy; unpack_(c, cx, cy);
                    const uint32_t ck = bfpack_(cy, cx);
                    zc0 = add2_(zc0,
                        bfexpand_(__shfl_xor_sync(0xffffffffu, ck, r)));
                }
                // fwd gather, round r+1
                {
                    const unsigned long long v =
                        bfexpand_(__shfl_xor_sync(0xffffffffu, pkF, r + 1));
                    aA1 = fma2_(EAC[r + 1], v, aA1);
                    aB1 = fma2_(EBD[r + 1], v, aB1);
                }
                // bwd scatter, round r+1
                {
                    const unsigned long long c =
                        fma2_(EAC[r + 1], wlo2, fma2_(EBD[r + 1], whi2, 0ull));
                    float cx, cy; unpack_(c, cx, cy);
                    const uint32_t ck = bfpack_(cy, cx);
                    zc1 = add2_(zc1,
                        bfexpand_(__shfl_xor_sync(0xffffffffu, ck, r + 1)));
                }
            }

            // ---- fwd epilogue ----
            float sa0, sa1, sb0, sb1;
            unpack_(add2_(aA0, aA1), sa0, sa1);
            unpack_(add2_(aB0, aB1), sb0, sb1);
            const bool  updF = (s + u) < nstF;
            const float rrF  = (u == 2) ? rfF : 1.0f;
            const float pubF_lo = (sa0 + sa1) * rrF * efFL[u];
            const float pubF_hi = (sb0 + sb1) * rrF * efFH[u];
            stF_lo = updF ? pubF_lo : stF_lo;
            stF_hi = updF ? pubF_hi : stF_hi;
            C2f = updF ? (C2f + SH2 + ((u == 2) ? lgF : 0.0f)) : C2f;
            pF_lo = pubF_lo; pF_hi = pubF_hi;
            pkF = bfpack_(pF_hi, pF_lo);

            // ---- bwd epilogue ----
            float zl0, zh0;
            unpack_(add2_(zc0, zc1), zl0, zh0);
            const bool  updB = (s + u) < nstB;
            const float rrB  = (u == 2) ? rfB : 1.0f;
            const float SrB_lo = zl0 * rrB;
            const float SrB_hi = zh0 * rrB;
            stB_lo = updB ? SrB_lo : stB_lo;
            stB_hi = updB ? SrB_hi : stB_hi;
            C2b = updB ? (C2b + SH2 + ((u == 2) ? lgB : 0.0f)) : C2b;
            wB_lo = SrB_lo * efBL[u];
            wB_hi = SrB_hi * efBH[u];

            // ---- feats pipelines (consumed 4 iterations later) ----
            efFL[u] = ex2f_(fmaf(fFL[u], L2E, -SH2));
            efFH[u] = ex2f_(fmaf(fFH[u], L2E, -SH2));
            const float* pfF = fs + ((size_t)clampi_(fidxF, 0, SEQ - 1) << 16);
            fFL[u] = __ldcs(pfF);
            fFH[u] = __ldcs(pfF + 32);
            ++fidxF;
            efBL[u] = ex2f_(fmaf(fBL[u], L2E, -SH2));
            efBH[u] = ex2f_(fmaf(fBH[u], L2E, -SH2));
            const float* pfB = fs + ((size_t)clampi_(fidxB, 0, SEQ - 1) << 16);
            fBL[u] = __ldcs(pfB);
            fBH[u] = __ldcs(pfB + 32);
            --fidxB;

            // ---- once per 4 steps: renorms (applied next block @u==2) ----
            if (u == 3) {
                const float MF  = fmaxf(wmax_(fmaxf(pF_lo, pF_hi)), 1e-30f);
                const float lF2 = lg2f_(MF);
                rfF = ex2f_(-lF2);  lgF = lF2;
                const float MB  = fmaxf(wmax_(fmaxf(wB_lo, wB_hi)), 1e-30f);
                const float lB2 = lg2f_(MB);
                rfB = ex2f_(-lB2);  lgB = lB2;
            }
        }
    }

    // ---- combine (in-warp): out = (C2f + C2b + lg2 <p_h, z_h>) * ln2 ----
    float ss = stF_lo * stB_lo + stF_hi * stB_hi;
#pragma unroll
    for (int d = 16; d; d >>= 1)
        ss += __shfl_xor_sync(0xffffffffu, ss, d);
    if (lane == 0) out[b] = (C2f + C2b + lg2f_(ss)) * LN2;
}

extern "C" void kernel_launch(void* const* d_in, const int* in_sizes, int n_in,
                              void* d_out, int out_size) {
    const float* feats = nullptr;
    const float* maskp = nullptr;
    const float* trans = nullptr;
    for (int i = 0; i < n_in; ++i) {
        if (in_sizes[i] == SEQ * BATCH * NTAG)      feats = (const float*)d_in[i];
        else if (in_sizes[i] == SEQ * BATCH)        maskp = (const float*)d_in[i];
        else if (in_sizes[i] == NTAG * NTAG)        trans = (const float*)d_in[i];
    }
    crf_main<<<BATCH, 32>>>(feats, maskp, trans, (float*)d_out);
}

// round 16
// speedup vs baseline: 1.1655x; 1.1655x over previous
#include <cuda_runtime.h>
#include <cstdint>

#define SEQ    512
#define BATCH  1024
#define NTAG   64
#define DEPTH  8
#define RPAD   68              // floats per batch-row in a ring slot (272B, 16B-aligned)
#define SLOTF  (16 * RPAD)     // floats per ring slot

__device__ __forceinline__ float ex2f_(float x) {
    float y; asm("ex2.approx.ftz.f32 %0, %1;" : "=f"(y) : "f"(x)); return y;
}
__device__ __forceinline__ float lg2f_(float x) {
    float y; asm("lg2.approx.ftz.f32 %0, %1;" : "=f"(y) : "f"(x)); return y;
}
// bf16x2 word: hi f32 -> high half, lo f32 -> low half
__device__ __forceinline__ uint32_t bfpack_(float hi, float lo) {
    uint32_t r;
    asm("cvt.rn.satfinite.bf16x2.f32 %0, %1, %2;" : "=r"(r) : "f"(hi), "f"(lo));
    return r;
}
__device__ __forceinline__ uint32_t smem_u32_(const void* p) {
    uint32_t a;
    asm("{ .reg .u64 t; cvta.to.shared.u64 t, %1; cvt.u32.u64 %0, t; }"
        : "=r"(a) : "l"(p));
    return a;
}
__device__ __forceinline__ void cpa16_(uint32_t dst, const float* src) {
    asm volatile("cp.async.cg.shared.global [%0], [%1], 16;" :: "r"(dst), "l"(src));
}
__device__ __forceinline__ void cpa_commit_() {
    asm volatile("cp.async.commit_group;" ::: "memory");
}
__device__ __forceinline__ void cpa_wait6_() {
    asm volatile("cp.async.wait_group 6;" ::: "memory");
}
__device__ __forceinline__ void lds64_(float& a, float& b, uint32_t addr) {
    asm volatile("ld.shared.v2.f32 {%0,%1}, [%2];" : "=f"(a), "=f"(b) : "r"(addr));
}
// D = A(bf16 m16k16) @ B(bf16 k16n8, col) + C, f32 accum
__device__ __forceinline__ void mma_(float* d, const uint32_t* a, const uint32_t* b,
                                     const float* c) {
    asm volatile(
        "mma.sync.aligned.m16n8k16.row.col.f32.bf16.bf16.f32 "
        "{%0,%1,%2,%3}, {%4,%5,%6,%7}, {%8,%9}, {%10,%11,%12,%13};"
        : "=f"(d[0]), "=f"(d[1]), "=f"(d[2]), "=f"(d[3])
        : "r"(a[0]), "r"(a[1]), "r"(a[2]), "r"(a[3]), "r"(b[0]), "r"(b[1]),
          "f"(c[0]), "f"(c[1]), "f"(c[2]), "f"(c[3]));
}

// One warp = 16 batches. State Q (16x64) lives in m16n8 D-fragments (8 n-tiles,
// f32). Step: pack Q -> A-frags (pure CVT, no shuffles: D n-tiles (2k,2k+1)
// ARE A k-tile k's layout), 32x mma bf16 vs resident E^T B-frags, multiply by
// ef (cp.async ring + ex2), per-row freeze/renorm/ledger (R8 scheme).
__global__ void __launch_bounds__(32)
crf_mma(const float* __restrict__ feats, const float* __restrict__ mask,
        const float* __restrict__ trans, float* __restrict__ out) {
    const int lane = threadIdx.x;
    const int g = lane >> 2, t = lane & 3;          // quad layout
    const int bbase = blockIdx.x * 16;

    __shared__ __align__(16) float ring[DEPTH * SLOTF];   // 34.8 KB

    const float LN2 = 0.6931471805599453f;
    const float L2E = 1.4426950408889634f;
    const float SH2 = 6.0f * L2E;

    // ---- per-batch lens from the monotone mask ----
    float part = 0.0f;
    {
        const int bc = lane & 15, sh = lane >> 4;
        const float* mp = mask + (size_t)sh * BATCH + bbase + bc;
#pragma unroll 8
        for (int k = 0; k < 256; ++k)
            part += __ldcs(mp + (size_t)2 * k * BATCH);
    }
    part += __shfl_xor_sync(0xffffffffu, part, 16);
    const int lenG = (int)(__shfl_sync(0xffffffffu, part, g) + 0.5f);
    const int lenH = (int)(__shfl_sync(0xffffffffu, part, g + 8) + 0.5f);
    float lmx = part;
#pragma unroll
    for (int d = 16; d; d >>= 1)
        lmx = fmaxf(lmx, __shfl_xor_sync(0xffffffffu, lmx, d));
    const int lenr = (((int)(lmx + 0.5f)) + 3) & ~3;

    // ---- resident B-fragments: B = E^T, B[k][n] = E[n][k] = exp(trans[n*64+k])
    uint32_t Bf[4][8][2];
#pragma unroll
    for (int kt = 0; kt < 4; ++kt)
#pragma unroll
        for (int nt = 0; nt < 8; ++nt) {
            const int n = nt * 8 + g;
            const int k0 = kt * 16 + 2 * t;
            Bf[kt][nt][0] = bfpack_(__expf(__ldg(trans + n * 64 + k0 + 1)),
                                    __expf(__ldg(trans + n * 64 + k0)));
            Bf[kt][nt][1] = bfpack_(__expf(__ldg(trans + n * 64 + k0 + 9)),
                                    __expf(__ldg(trans + n * 64 + k0 + 8)));
        }
    // final-row factors exp(T[END=1][col]) at this thread's D columns
    float eTa[8], eTb[8];
#pragma unroll
    for (int nt = 0; nt < 8; ++nt) {
        eTa[nt] = __expf(__ldg(trans + 64 + nt * 8 + 2 * t));
        eTb[nt] = __expf(__ldg(trans + 64 + nt * 8 + 2 * t + 1));
    }

    // ---- feats ring prologue (7 slots in flight) ----
    const uint32_t rbase = smem_u32_(ring);
    const int rrow = lane & 15, rhalf = lane >> 4;
    const uint32_t dstb = rbase + (uint32_t)rrow * (RPAD * 4) + (uint32_t)rhalf * 128;
    const float* srcb = feats + (size_t)(bbase + rrow) * 64 + rhalf * 32;
#pragma unroll
    for (int sl = 0; sl < DEPTH - 1; ++sl) {
        const float* src = srcb + ((size_t)sl << 16);
#pragma unroll
        for (int c = 0; c < 8; ++c)
            cpa16_(dstb + (uint32_t)sl * (SLOTF * 4) + c * 16, src + c * 4);
        cpa_commit_();
    }
    cpa_wait6_();
    __syncwarp();

    // ---- state Q in D layout: q[nt*4+c]; c0,c1=row g cols 2t,2t+1; c2,c3=row g+8
    float q[32];
#pragma unroll
    for (int i = 0; i < 32; ++i) q[i] = 0.0f;
    if (t == 0) { q[0] = 1.0f; q[2] = 1.0f; }   // one-hot at tag 0 (START)

    float C2g = 0.0f, C2h = 0.0f;
    float rfG = 1.0f, rfH = 1.0f, lgG = 0.0f, lgH = 0.0f;
    const float fz = 0.0f;
    const float zero4[4] = {fz, fz, fz, fz};

#pragma unroll 1
    for (int s0 = 0; s0 < lenr; s0 += 4) {
#pragma unroll
        for (int u = 0; u < 4; ++u) {
            const int s = s0 + u;

            // ef for this step (slot s): 16 LDS.64 + 32 FFMA + 32 ex2
            float efg[16], efh[16];
            {
                const uint32_t sb = rbase + (uint32_t)(s & 7) * (SLOTF * 4);
                const uint32_t ag = sb + (uint32_t)g * (RPAD * 4) + 2 * t * 4;
                const uint32_t ah = sb + (uint32_t)(g + 8) * (RPAD * 4) + 2 * t * 4;
#pragma unroll
                for (int nt = 0; nt < 8; ++nt) {
                    float f0, f1;
                    lds64_(f0, f1, ag + nt * 32);
                    efg[2 * nt]     = ex2f_(fmaf(f0, L2E, -SH2));
                    efg[2 * nt + 1] = ex2f_(fmaf(f1, L2E, -SH2));
                    lds64_(f0, f1, ah + nt * 32);
                    efh[2 * nt]     = ex2f_(fmaf(f0, L2E, -SH2));
                    efh[2 * nt + 1] = ex2f_(fmaf(f1, L2E, -SH2));
                }
            }

            // pack Q -> A frags (D n-tiles 2kt,2kt+1 -> A k-tile kt)
            uint32_t a[4][4];
#pragma unroll
            for (int kt = 0; kt < 4; ++kt) {
                a[kt][0] = bfpack_(q[(2 * kt) * 4 + 1],     q[(2 * kt) * 4 + 0]);
                a[kt][1] = bfpack_(q[(2 * kt) * 4 + 3],     q[(2 * kt) * 4 + 2]);
                a[kt][2] = bfpack_(q[(2 * kt + 1) * 4 + 1], q[(2 * kt + 1) * 4 + 0]);
                a[kt][3] = bfpack_(q[(2 * kt + 1) * 4 + 3], q[(2 * kt + 1) * 4 + 2]);
            }

            // Dn = Q @ E^T : 32 MMAs, 4-deep k-accumulation per n-tile
            float dn[32];
#pragma unroll
            for (int nt = 0; nt < 8; ++nt) {
                mma_(dn + nt * 4, a[0], Bf[0][nt], zero4);
#pragma unroll
                for (int kt = 1; kt < 4; ++kt)
                    mma_(dn + nt * 4, a[kt], Bf[kt][nt], dn + nt * 4);
            }

            // Q' = ef ∘ Dn (+ lagged renorm at u==2); per-row freeze
            const bool updG = s < lenG;
            const bool updH = s < lenH;
            const float rg = (u == 2) ? rfG : 1.0f;
            const float rh = (u == 2) ? rfH : 1.0f;
#pragma unroll
            for (int nt = 0; nt < 8; ++nt) {
                const float n0 = dn[nt * 4 + 0] * (efg[2 * nt] * rg);
                const float n1 = dn[nt * 4 + 1] * (efg[2 * nt + 1] * rg);
                const float n2 = dn[nt * 4 + 2] * (efh[2 * nt] * rh);
                const float n3 = dn[nt * 4 + 3] * (efh[2 * nt + 1] * rh);
                q[nt * 4 + 0] = updG ? n0 : q[nt * 4 + 0];
                q[nt * 4 + 1] = updG ? n1 : q[nt * 4 + 1];
                q[nt * 4 + 2] = updH ? n2 : q[nt * 4 + 2];
                q[nt * 4 + 3] = updH ? n3 : q[nt * 4 + 3];
            }
            C2g = updG ? (C2g + SH2 + ((u == 2) ? lgG : 0.0f)) : C2g;
            C2h = updH ? (C2h + SH2 + ((u == 2) ? lgH : 0.0f)) : C2h;

            // stream: prefetch slot s+7, retire; one syncwarp for cross-thread
            // visibility of cp.async data
            int sp = s + DEPTH - 1;
            if (sp > SEQ - 1) sp = SEQ - 1;
            {
                const float* src = srcb + ((size_t)sp << 16);
                const uint32_t dst =
                    dstb + (uint32_t)((s + DEPTH - 1) & 7) * (SLOTF * 4);
#pragma unroll
                for (int c = 0; c < 8; ++c)
                    cpa16_(dst + c * 16, src + c * 4);
            }
            cpa_commit_();
            cpa_wait6_();
            __syncwarp();

            // once per 4 steps: measure per-row renorm (applied next block @u==2)
            if (u == 3) {
                float mg = q[0], mh = q[2];
#pragma unroll
                for (int nt = 0; nt < 8; ++nt) {
                    mg = fmaxf(mg, fmaxf(q[nt * 4 + 0], q[nt * 4 + 1]));
                    mh = fmaxf(mh, fmaxf(q[nt * 4 + 2], q[nt * 4 + 3]));
                }
                mg = fmaxf(mg, __shfl_xor_sync(0xffffffffu, mg, 1));
                mg = fmaxf(mg, __shfl_xor_sync(0xffffffffu, mg, 2));
                mh = fmaxf(mh, __shfl_xor_sync(0xffffffffu, mh, 1));
                mh = fmaxf(mh, __shfl_xor_sync(0xffffffffu, mh, 2));
                const float lgn = lg2f_(fmaxf(mg, 1e-30f));
                rfG = ex2f_(-lgn);  lgG = lgn;
                const float lhn = lg2f_(fmaxf(mh, 1e-30f));
                rfH = ex2f_(-lhn);  lgH = lhn;
            }
        }
    }

    // ---- out[b] = (C2 + lg2( sum_j q[b][j] * exp(T[END][j]) )) * ln2 ----
    float sg = 0.0f, sh = 0.0f;
#pragma unroll
    for (int nt = 0; nt < 8; ++nt) {
        sg = fmaf(q[nt * 4 + 0], eTa[nt], fmaf(q[nt * 4 + 1], eTb[nt], sg));
        sh = fmaf(q[nt * 4 + 2], eTa[nt], fmaf(q[nt * 4 + 3], eTb[nt], sh));
    }
    sg += __shfl_xor_sync(0xffffffffu, sg, 1);
    sg += __shfl_xor_sync(0xffffffffu, sg, 2);
    sh += __shfl_xor_sync(0xffffffffu, sh, 1);
    sh += __shfl_xor_sync(0xffffffffu, sh, 2);
    if (t == 0) {
        out[bbase + g]     = (C2g + lg2f_(sg)) * LN2;
        out[bbase + 8 + g] = (C2h + lg2f_(sh)) * LN2;
    }
}

extern "C" void kernel_launch(void* const* d_in, const int* in_sizes, int n_in,
                              void* d_out, int out_size) {
    const float* feats = nullptr;
    const float* maskp = nullptr;
    const float* trans = nullptr;
    for (int i = 0; i < n_in; ++i) {
        if (in_sizes[i] == SEQ * BATCH * NTAG)      feats = (const float*)d_in[i];
        else if (in_sizes[i] == SEQ * BATCH)        maskp = (const float*)d_in[i];
        else if (in_sizes[i] == NTAG * NTAG)        trans = (const float*)d_in[i];
    }
    crf_mma<<<BATCH / 16, 32>>>(feats, maskp, trans, (float*)d_out);
}

// round 17
// speedup vs baseline: 1.6000x; 1.3728x over previous
#include <cuda_runtime.h>
#include <cstdint>

#define SEQ    512
#define BATCH  1024
#define NTAG   64
#define DEPTH  5
#define RPAD   68              // floats per batch-row in a ring slot
#define SLOTF  (16 * RPAD)     // floats per ring slot (4352 B)

__device__ __forceinline__ float ex2f_(float x) {
    float y; asm("ex2.approx.ftz.f32 %0, %1;" : "=f"(y) : "f"(x)); return y;
}
__device__ __forceinline__ float lg2f_(float x) {
    float y; asm("lg2.approx.ftz.f32 %0, %1;" : "=f"(y) : "f"(x)); return y;
}
__device__ __forceinline__ uint32_t bfpack_(float hi, float lo) {
    uint32_t r;
    asm("cvt.rn.satfinite.bf16x2.f32 %0, %1, %2;" : "=r"(r) : "f"(hi), "f"(lo));
    return r;
}
__device__ __forceinline__ uint32_t smem_u32_(const void* p) {
    uint32_t a;
    asm("{ .reg .u64 t; cvta.to.shared.u64 t, %1; cvt.u32.u64 %0, t; }"
        : "=r"(a) : "l"(p));
    return a;
}
__device__ __forceinline__ void cpa16_(uint32_t dst, const float* src) {
    asm volatile("cp.async.cg.shared.global [%0], [%1], 16;" :: "r"(dst), "l"(src));
}
__device__ __forceinline__ void cpa_commit_() {
    asm volatile("cp.async.commit_group;" ::: "memory");
}
__device__ __forceinline__ void cpa_wait3_() {
    asm volatile("cp.async.wait_group 3;" ::: "memory");
}
__device__ __forceinline__ void lds64_(float& a, float& b, uint32_t addr) {
    asm volatile("ld.shared.v2.f32 {%0,%1}, [%2];" : "=f"(a), "=f"(b) : "r"(addr));
}
__device__ __forceinline__ void mma_(float* d, const uint32_t* a, const uint32_t* b,
                                     const float* c) {
    asm volatile(
        "mma.sync.aligned.m16n8k16.row.col.f32.bf16.bf16.f32 "
        "{%0,%1,%2,%3}, {%4,%5,%6,%7}, {%8,%9}, {%10,%11,%12,%13};"
        : "=f"(d[0]), "=f"(d[1]), "=f"(d[2]), "=f"(d[3])
        : "r"(a[0]), "r"(a[1]), "r"(a[2]), "r"(a[3]), "r"(b[0]), "r"(b[1]),
          "f"(c[0]), "f"(c[1]), "f"(c[2]), "f"(c[3]));
}
__device__ __forceinline__ int clampi_(int v, int lo, int hi) {
    return v < lo ? lo : (v > hi ? hi : v);
}

// One CTA = 64 threads = 16 batches.
//   warp 0 (fwd): p_{t+1} = ef_t ∘ (P @ E^T),  t = 0 .. h-1   (B = E^T)
//   warp 1 (bwd): z_t = (ef_t ∘ z_{t+1}) @ E,  t = len-1 .. h (B = E)
//   out[b] = (C2f + C2b + lg2 <p_h, z_h>) * ln2 — exact (R13-validated math)
// Engine per warp = R16 MMA step (validated): D-frag state, CVT-only repack
// to A-frags, 32 bf16 MMAs vs resident B-frags, ef via cp.async ring + ex2,
// per-row freeze / lagged renorm / ledger. Critical path: 512 -> ~260 steps.
__global__ void __launch_bounds__(64)
crf_mma(const float* __restrict__ feats, const float* __restrict__ mask,
        const float* __restrict__ trans, float* __restrict__ out) {
    const int lane = threadIdx.x & 31;
    const int dir  = threadIdx.x >> 5;          // 0 = fwd, 1 = bwd
    const int g = lane >> 2, t = lane & 3;
    const int bbase = blockIdx.x * 16;

    __shared__ __align__(16) float ring[2 * DEPTH * SLOTF];  // 43.5 KB
    __shared__ float zst[16][NTAG];                          // bwd z_h
    __shared__ float c2b_s[16];

    const float LN2 = 0.6931471805599453f;
    const float L2E = 1.4426950408889634f;
    const float SH2 = 6.0f * L2E;

    // ---- per-batch lens (monotone mask column sums, 2 threads per row) ----
    float part = 0.0f;
    {
        const int bc = lane & 15, sh = lane >> 4;
        const float* mp = mask + (size_t)sh * BATCH + bbase + bc;
#pragma unroll 8
        for (int k = 0; k < 256; ++k)
            part += __ldcs(mp + (size_t)2 * k * BATCH);
    }
    part += __shfl_xor_sync(0xffffffffu, part, 16);
    const int lenRR = (int)(part + 0.5f);             // len of row (lane&15)
    const int hRR   = (lenRR + 1) >> 1;
    const int nstRR = dir ? (lenRR - hRR) : hRR;      // my row's step count
    // rows g and g+8 for freeze / ledger
    const int lenG = (int)(__shfl_sync(0xffffffffu, part, g) + 0.5f);
    const int lenH = (int)(__shfl_sync(0xffffffffu, part, g + 8) + 0.5f);
    const int hG = (lenG + 1) >> 1, hH = (lenH + 1) >> 1;
    const int nstG = dir ? (lenG - hG) : hG;
    const int nstH = dir ? (lenH - hH) : hH;
    // warp loop bound
    float nmx = (float)nstRR;
#pragma unroll
    for (int d = 16; d; d >>= 1)
        nmx = fmaxf(nmx, __shfl_xor_sync(0xffffffffu, nmx, d));
    const int lenr = (((int)(nmx + 0.5f)) + 3) & ~3;

    // ---- resident B-fragments ----
    // fwd: B[k][n] = E[n][k] = exp(trans[n*64+k]);  bwd: B[k][n] = E[k][n]
    uint32_t Bf[4][8][2];
#pragma unroll
    for (int kt = 0; kt < 4; ++kt)
#pragma unroll
        for (int nt = 0; nt < 8; ++nt) {
            const int n = nt * 8 + g;
            const int k0 = kt * 16 + 2 * t;
            if (dir == 0) {
                Bf[kt][nt][0] = bfpack_(__expf(__ldg(trans + n * 64 + k0 + 1)),
                                        __expf(__ldg(trans + n * 64 + k0)));
                Bf[kt][nt][1] = bfpack_(__expf(__ldg(trans + n * 64 + k0 + 9)),
                                        __expf(__ldg(trans + n * 64 + k0 + 8)));
            } else {
                Bf[kt][nt][0] = bfpack_(__expf(__ldg(trans + (k0 + 1) * 64 + n)),
                                        __expf(__ldg(trans + k0 * 64 + n)));
                Bf[kt][nt][1] = bfpack_(__expf(__ldg(trans + (k0 + 9) * 64 + n)),
                                        __expf(__ldg(trans + (k0 + 8) * 64 + n)));
            }
        }

    // ---- feats ring prologue ----
    const uint32_t rbase = smem_u32_(ring) + (uint32_t)dir * (DEPTH * SLOTF * 4);
    const int rrow = lane & 15, rhalf = lane >> 4;
    const uint32_t dstb = rbase + (uint32_t)rrow * (RPAD * 4) + (uint32_t)rhalf * 128;
    const float* srcb = feats + (size_t)(bbase + rrow) * NTAG + rhalf * 32;
    // step index streamed into slot sl:
    //   fwd: sl ;  bwd: len_rr - 2 - sl  (clamped)
#pragma unroll
    for (int sl = 0; sl < DEPTH - 1; ++sl) {
        const int st = dir ? clampi_(lenRR - 2 - sl, 0, SEQ - 1) : sl;
        const float* src = srcb + ((size_t)st << 16);
#pragma unroll
        for (int c = 0; c < 8; ++c)
            cpa16_(dstb + (uint32_t)sl * (SLOTF * 4) + c * 16, src + c * 4);
        cpa_commit_();
    }
    cpa_wait3_();
    __syncwarp();

    // ---- state q (transported vector) in D layout ----
    float q[32];
    if (dir == 0) {
#pragma unroll
        for (int i = 0; i < 32; ++i) q[i] = 0.0f;
        if (t == 0) { q[0] = 1.0f; q[2] = 1.0f; }    // one-hot at START=0
    } else {
        // w_0 = ef_{len-1} ∘ z_len,  z_len[i] = exp(T[END=1][i])
#pragma unroll
        for (int nt = 0; nt < 8; ++nt) {
            const int c0 = nt * 8 + 2 * t;
            const float z0 = __expf(__ldg(trans + 64 + c0));
            const float z1 = __expf(__ldg(trans + 64 + c0 + 1));
            const float* fg = feats + ((size_t)(lenG - 1) << 16)
                              + (size_t)(bbase + g) * NTAG + c0;
            const float* fh = feats + ((size_t)(lenH - 1) << 16)
                              + (size_t)(bbase + 8 + g) * NTAG + c0;
            q[nt * 4 + 0] = z0 * ex2f_(fmaf(__ldcs(fg),     L2E, -SH2));
            q[nt * 4 + 1] = z1 * ex2f_(fmaf(__ldcs(fg + 1), L2E, -SH2));
            q[nt * 4 + 2] = z0 * ex2f_(fmaf(__ldcs(fh),     L2E, -SH2));
            q[nt * 4 + 3] = z1 * ex2f_(fmaf(__ldcs(fh + 1), L2E, -SH2));
        }
    }
    float st[32];
#pragma unroll
    for (int i = 0; i < 32; ++i) st[i] = q[i];

    float C2g = 0.0f, C2h = 0.0f;
    float rfG = 1.0f, rfH = 1.0f, lgG = 0.0f, lgH = 0.0f;
    const float zero4[4] = {0.0f, 0.0f, 0.0f, 0.0f};
    int slot_c = 0, slot_p = DEPTH - 1;              // consumed / prefetched

#pragma unroll 1
    for (int s0 = 0; s0 < lenr; s0 += 4) {
#pragma unroll
        for (int u = 0; u < 4; ++u) {
            const int s = s0 + u;

            // ef for this step from ring slot slot_c
            float efg[16], efh[16];
            {
                const uint32_t sb = rbase + (uint32_t)slot_c * (SLOTF * 4);
                const uint32_t ag = sb + (uint32_t)g * (RPAD * 4) + 2 * t * 4;
                const uint32_t ah = sb + (uint32_t)(g + 8) * (RPAD * 4) + 2 * t * 4;
#pragma unroll
                for (int nt = 0; nt < 8; ++nt) {
                    float f0, f1;
                    lds64_(f0, f1, ag + nt * 32);
                    efg[2 * nt]     = ex2f_(fmaf(f0, L2E, -SH2));
                    efg[2 * nt + 1] = ex2f_(fmaf(f1, L2E, -SH2));
                    lds64_(f0, f1, ah + nt * 32);
                    efh[2 * nt]     = ex2f_(fmaf(f0, L2E, -SH2));
                    efh[2 * nt + 1] = ex2f_(fmaf(f1, L2E, -SH2));
                }
            }

            // pack q -> A frags (pure CVT; D n-tiles (2kt,2kt+1) = A k-tile kt)
            uint32_t a[4][4];
#pragma unroll
            for (int kt = 0; kt < 4; ++kt) {
                a[kt][0] = bfpack_(q[(2 * kt) * 4 + 1],     q[(2 * kt) * 4 + 0]);
                a[kt][1] = bfpack_(q[(2 * kt) * 4 + 3],     q[(2 * kt) * 4 + 2]);
                a[kt][2] = bfpack_(q[(2 * kt + 1) * 4 + 1], q[(2 * kt + 1) * 4 + 0]);
                a[kt][3] = bfpack_(q[(2 * kt + 1) * 4 + 3], q[(2 * kt + 1) * 4 + 2]);
            }

            // D = q @ B : 32 MMAs
            float dn[32];
#pragma unroll
            for (int nt = 0; nt < 8; ++nt) {
                mma_(dn + nt * 4, a[0], Bf[0][nt], zero4);
#pragma unroll
                for (int kt = 1; kt < 4; ++kt)
                    mma_(dn + nt * 4, a[kt], Bf[kt][nt], dn + nt * 4);
            }

            // snapshot + transported update (fwd: st = ef∘D; bwd: st = D)
            const bool updG = s < nstG;
            const bool updH = s < nstH;
            const float rg = (u == 2) ? rfG : 1.0f;
            const float rh = (u == 2) ? rfH : 1.0f;
#pragma unroll
            for (int nt = 0; nt < 8; ++nt) {
                const float d0 = dn[nt * 4 + 0] * rg;
                const float d1 = dn[nt * 4 + 1] * rg;
                const float d2 = dn[nt * 4 + 2] * rh;
                const float d3 = dn[nt * 4 + 3] * rh;
                const float p0 = d0 * efg[2 * nt];
                const float p1 = d1 * efg[2 * nt + 1];
                const float p2 = d2 * efh[2 * nt];
                const float p3 = d3 * efh[2 * nt + 1];
                const float c0 = dir ? d0 : p0;
                const float c1 = dir ? d1 : p1;
                const float c2 = dir ? d2 : p2;
                const float c3 = dir ? d3 : p3;
                st[nt * 4 + 0] = updG ? c0 : st[nt * 4 + 0];
                st[nt * 4 + 1] = updG ? c1 : st[nt * 4 + 1];
                st[nt * 4 + 2] = updH ? c2 : st[nt * 4 + 2];
                st[nt * 4 + 3] = updH ? c3 : st[nt * 4 + 3];
                q[nt * 4 + 0] = p0;
                q[nt * 4 + 1] = p1;
                q[nt * 4 + 2] = p2;
                q[nt * 4 + 3] = p3;
            }
            C2g = updG ? (C2g + SH2 + ((u == 2) ? lgG : 0.0f)) : C2g;
            C2h = updH ? (C2h + SH2 + ((u == 2) ? lgH : 0.0f)) : C2h;

            // stream: prefetch next slot, retire current
            {
                const int sl = s + DEPTH - 1;
                const int stp = dir ? clampi_(lenRR - 2 - sl, 0, SEQ - 1)
                                    : clampi_(sl, 0, SEQ - 1);
                const float* src = srcb + ((size_t)stp << 16);
                if (++slot_p == DEPTH) slot_p = 0;
                const uint32_t dst = dstb + (uint32_t)slot_p * (SLOTF * 4);
#pragma unroll
                for (int c = 0; c < 8; ++c)
                    cpa16_(dst + c * 16, src + c * 4);
            }
            cpa_commit_();
            cpa_wait3_();
            __syncwarp();
            if (++slot_c == DEPTH) slot_c = 0;

            // once per 4 steps: per-row renorm (applied next block @u==2)
            if (u == 3) {
                float mg = q[0], mh = q[2];
#pragma unroll
                for (int nt = 0; nt < 8; ++nt) {
                    mg = fmaxf(mg, fmaxf(q[nt * 4 + 0], q[nt * 4 + 1]));
                    mh = fmaxf(mh, fmaxf(q[nt * 4 + 2], q[nt * 4 + 3]));
                }
                mg = fmaxf(mg, __shfl_xor_sync(0xffffffffu, mg, 1));
                mg = fmaxf(mg, __shfl_xor_sync(0xffffffffu, mg, 2));
                mh = fmaxf(mh, __shfl_xor_sync(0xffffffffu, mh, 1));
                mh = fmaxf(mh, __shfl_xor_sync(0xffffffffu, mh, 2));
                const float lgn = lg2f_(fmaxf(mg, 1e-30f));
                rfG = ex2f_(-lgn);  lgG = lgn;
                const float lhn = lg2f_(fmaxf(mh, 1e-30f));
                rfH = ex2f_(-lhn);  lgH = lhn;
            }
        }
    }

    // ---- combine: out[b] = (C2f + C2b + lg2 <p_h, z_h>) * ln2 ----
    if (dir == 1) {
#pragma unroll
        for (int nt = 0; nt < 8; ++nt) {
            const int c0 = nt * 8 + 2 * t;
            zst[g][c0]         = st[nt * 4 + 0];
            zst[g][c0 + 1]     = st[nt * 4 + 1];
            zst[g + 8][c0]     = st[nt * 4 + 2];
            zst[g + 8][c0 + 1] = st[nt * 4 + 3];
        }
        if (t == 0) { c2b_s[g] = C2g; c2b_s[g + 8] = C2h; }
    }
    __syncthreads();
    if (dir == 0) {
        float sg = 0.0f, sh = 0.0f;
#pragma unroll
        for (int nt = 0; nt < 8; ++nt) {
            const int c0 = nt * 8 + 2 * t;
            sg = fmaf(st[nt * 4 + 0], zst[g][c0],
                 fmaf(st[nt * 4 + 1], zst[g][c0 + 1], sg));
            sh = fmaf(st[nt * 4 + 2], zst[g + 8][c0],
                 fmaf(st[nt * 4 + 3], zst[g + 8][c0 + 1], sh));
        }
        sg += __shfl_xor_sync(0xffffffffu, sg, 1);
        sg += __shfl_xor_sync(0xffffffffu, sg, 2);
        sh += __shfl_xor_sync(0xffffffffu, sh, 1);
        sh += __shfl_xor_sync(0xffffffffu, sh, 2);
        if (t == 0) {
            out[bbase + g]     = (C2g + c2b_s[g]     + lg2f_(sg)) * LN2;
            out[bbase + 8 + g] = (C2h + c2b_s[g + 8] + lg2f_(sh)) * LN2;
        }
    }
}

extern "C" void kernel_launch(void* const* d_in, const int* in_sizes, int n_in,
                              void* d_out, int out_size) {
    const float* feats = nullptr;
    const float* maskp = nullptr;
    const float* trans = nullptr;
    for (int i = 0; i < n_in; ++i) {
        if (in_sizes[i] == SEQ * BATCH * NTAG)      feats = (const float*)d_in[i];
        else if (in_sizes[i] == SEQ * BATCH)        maskp = (const float*)d_in[i];
        else if (in_sizes[i] == NTAG * NTAG)        trans = (const float*)d_in[i];
    }
    crf_mma<<<BATCH / 16, 64>>>(feats, maskp, trans, (float*)d_out);
}